// round 5
// baseline (speedup 1.0000x reference)
#include <cuda_runtime.h>
#include <math.h>

#define NB 4
#define NL 2048
#define ND 1024
#define NH 16
#define DH 64
#define ND3 (3*ND)

// Scratch (allocation-free: __device__ globals)
__device__ float    g_qkv[(size_t)NB*NL*ND3];     // fp32 qkv
__device__ unsigned g_xt [(size_t)NB*NL*ND];      // x in tf32
__device__ unsigned g_wqkvt[(size_t)ND3*ND];      // W_qkv^T tf32 [N][K]
__device__ unsigned g_wprojt[(size_t)ND*ND];      // W_proj^T tf32 [N][K]
__device__ unsigned g_q [(size_t)NB*NH*NL*DH];    // roped Q tf32 [b,h,l,d]
__device__ unsigned g_k [(size_t)NB*NH*NL*DH];    // roped K tf32 [b,h,l,d]
__device__ unsigned g_vt[(size_t)NB*NH*DH*NL];    // V^T tf32 [b,h,d,key'(perm)]
__device__ unsigned g_attn[(size_t)NB*NL*ND];     // attn out tf32 [b,l,nd]

__device__ __forceinline__ unsigned f2tf(float f) {
    unsigned u;
    asm("cvt.rna.tf32.f32 %0, %1;" : "=r"(u) : "f"(f));
    return u;
}
__device__ __forceinline__ float ex2(float x) {
    float y;
    asm("ex2.approx.f32 %0, %1;" : "=f"(y) : "f"(x));
    return y;
}
__device__ __forceinline__ void mma8(float* d, const unsigned* a,
                                     unsigned b0, unsigned b1) {
    asm volatile(
        "mma.sync.aligned.m16n8k8.row.col.f32.tf32.tf32.f32 "
        "{%0,%1,%2,%3}, {%4,%5,%6,%7}, {%8,%9}, {%0,%1,%2,%3};"
        : "+f"(d[0]), "+f"(d[1]), "+f"(d[2]), "+f"(d[3])
        : "r"(a[0]), "r"(a[1]), "r"(a[2]), "r"(a[3]), "r"(b0), "r"(b1));
}
__device__ __forceinline__ void ldsm4(unsigned* r, unsigned addr) {
    asm volatile(
        "ldmatrix.sync.aligned.m8n8.x4.shared.b16 {%0,%1,%2,%3}, [%4];"
        : "=r"(r[0]), "=r"(r[1]), "=r"(r[2]), "=r"(r[3]) : "r"(addr));
}
__device__ __forceinline__ void cpa16(unsigned dst, const void* src) {
    asm volatile("cp.async.cg.shared.global [%0], [%1], 16;"
                 :: "r"(dst), "l"(src));
}
#define CP_COMMIT() asm volatile("cp.async.commit_group;")
#define CP_WAIT1()  asm volatile("cp.async.wait_group 1;")
#define CP_WAIT0()  asm volatile("cp.async.wait_group 0;")

// ---------------------------------------------------------------------------
// Prep: fp32 -> tf32 bulk convert (vectorized)
// ---------------------------------------------------------------------------
__global__ void conv_tf32(const float* __restrict__ src,
                          unsigned* __restrict__ dst, int n4)
{
    int i = blockIdx.x * blockDim.x + threadIdx.x;
    if (i < n4) {
        float4 v = ((const float4*)src)[i];
        ((uint4*)dst)[i] = make_uint4(f2tf(v.x), f2tf(v.y),
                                      f2tf(v.z), f2tf(v.w));
    }
}

// ---------------------------------------------------------------------------
// Prep: W [K][N] -> Wt [N][K] tf32
// ---------------------------------------------------------------------------
__global__ __launch_bounds__(256) void wtrans(
    const float* __restrict__ W, unsigned* __restrict__ Wt, int K, int N)
{
    __shared__ float sm[32][33];
    int tx = threadIdx.x & 31, ty = threadIdx.x >> 5;
    int n0 = blockIdx.x * 32, k0 = blockIdx.y * 32;
#pragma unroll
    for (int j = 0; j < 4; j++)
        sm[ty + 8 * j][tx] = W[(size_t)(k0 + ty + 8 * j) * N + n0 + tx];
    __syncthreads();
#pragma unroll
    for (int j = 0; j < 4; j++)
        Wt[(size_t)(n0 + ty + 8 * j) * K + k0 + tx] = f2tf(sm[tx][ty + 8 * j]);
}

// ---------------------------------------------------------------------------
// TF32 GEMM + bias: C[M][N] = A[M][K] @ Bt[N][K]^T + bias.
// A,Bt pre-converted tf32. CTA 128x128, BK=32, cp.async double buffer,
// all operands via ldmatrix. 8 warps (4m x 2n), warp tile 32x64. 2 CTA/SM.
// ---------------------------------------------------------------------------
__global__ __launch_bounds__(256, 2) void gemm_tf32(
    const unsigned* __restrict__ A, const unsigned* __restrict__ Bt,
    const float* __restrict__ bias, float* __restrict__ C,
    int M, int N, int K)
{
    extern __shared__ unsigned sh[];
    // per buf: As [128][36], Bs [128][36]
    const int tid = threadIdx.x;
    const int lane = tid & 31, wid = tid >> 5;
    const int wm = wid >> 1, wn = wid & 1;
    const int g = lane >> 2, t = lane & 3;
    const unsigned sh0 = (unsigned)__cvta_generic_to_shared(sh);

    const unsigned* Ag = A + (size_t)blockIdx.y * 128 * K;
    const unsigned* Bg = Bt + (size_t)blockIdx.x * 128 * K;

    float acc[2][8][4];
#pragma unroll
    for (int mf = 0; mf < 2; mf++)
#pragma unroll
        for (int nf = 0; nf < 8; nf++)
#pragma unroll
            for (int i = 0; i < 4; i++) acc[mf][nf][i] = 0.f;

    const int crow = tid >> 3, ck = (tid & 7) << 2;

    auto copy_tile = [&](int tile, int buf) {
        unsigned as = sh0 + buf * (2 * 4608 * 4);
        unsigned bs = as + 4608 * 4;
        const unsigned* Asrc = Ag + tile * 32;
        const unsigned* Bsrc = Bg + tile * 32;
#pragma unroll
        for (int i = 0; i < 4; i++) {
            int r = crow + i * 32;
            cpa16(as + (r * 36 + ck) * 4, Asrc + (size_t)r * K + ck);
            cpa16(bs + (r * 36 + ck) * 4, Bsrc + (size_t)r * K + ck);
        }
    };

    const int ar_ = wm * 32 + (lane & 15), ac_ = (lane >> 4) << 2;
    const int br_ = wn * 64 + (lane & 7) + ((lane & 16) ? 8 : 0);
    const int bc_ = (lane & 8) ? 4 : 0;

    copy_tile(0, 0);
    CP_COMMIT();

    const int nt = K / 32;
    int buf = 0;
    for (int tile = 0; tile < nt; tile++) {
        if (tile + 1 < nt) {
            copy_tile(tile + 1, buf ^ 1);
            CP_COMMIT();
            CP_WAIT1();
        } else {
            CP_WAIT0();
        }
        __syncthreads();

        unsigned as = sh0 + buf * (2 * 4608 * 4);
        unsigned bs = as + 4608 * 4;
        unsigned ab0 = as + (ar_ * 36 + ac_) * 4;
        unsigned ab1 = as + ((ar_ + 16) * 36 + ac_) * 4;
        unsigned bb  = bs + (br_ * 36 + bc_) * 4;

#pragma unroll
        for (int kc = 0; kc < 4; kc++) {
            const unsigned kadd = kc * 32;
            unsigned a[2][4];
            ldsm4(a[0], ab0 + kadd);
            ldsm4(a[1], ab1 + kadd);
#pragma unroll
            for (int nfp = 0; nfp < 4; nfp++) {
                unsigned bk[4];
                ldsm4(bk, bb + nfp * (16 * 36 * 4) + kadd);
                mma8(acc[0][2 * nfp],     a[0], bk[0], bk[1]);
                mma8(acc[1][2 * nfp],     a[1], bk[0], bk[1]);
                mma8(acc[0][2 * nfp + 1], a[0], bk[2], bk[3]);
                mma8(acc[1][2 * nfp + 1], a[1], bk[2], bk[3]);
            }
        }
        __syncthreads();
        buf ^= 1;
    }

#pragma unroll
    for (int mf = 0; mf < 2; mf++) {
        int row = blockIdx.y * 128 + wm * 32 + mf * 16 + g;
#pragma unroll
        for (int nf = 0; nf < 8; nf++) {
            int col = blockIdx.x * 128 + wn * 64 + nf * 8 + 2 * t;
            float b0 = bias[col], b1 = bias[col + 1];
            *(float2*)(C + (size_t)row * N + col) =
                make_float2(acc[mf][nf][0] + b0, acc[mf][nf][1] + b1);
            *(float2*)(C + (size_t)(row + 8) * N + col) =
                make_float2(acc[mf][nf][2] + b0, acc[mf][nf][3] + b1);
        }
    }
}

// ---------------------------------------------------------------------------
// RoPE: qkv fp32 -> roped Q,K tf32 in [b,h,l,d]
// ---------------------------------------------------------------------------
__global__ void rope_kernel(const float* __restrict__ qkv,
                            unsigned* __restrict__ Qo,
                            unsigned* __restrict__ Ko)
{
    int idx = blockIdx.x * blockDim.x + threadIdx.x;
    const int total = NB * NL * NH * (DH / 2);
    if (idx >= total) return;
    int i = idx & 31;
    int h = (idx >> 5) & 15;
    int l = (idx >> 9) & (NL - 1);
    int b = idx >> 20;

    float inv = powf(10000.0f, -(float)(2 * i) / (float)DH);
    float ang = (float)l * inv;
    float sn, cs;
    sincosf(ang, &sn, &cs);

    const float* base = qkv + (size_t)(b * NL + l) * ND3 + h * DH + 2 * i;
    float2 q = *(const float2*)(base);
    float2 k = *(const float2*)(base + ND);
    size_t o = ((size_t)(b * NH + h) * NL + l) * DH + 2 * i;
    *(uint2*)(Qo + o) = make_uint2(f2tf(q.x * cs - q.y * sn),
                                   f2tf(q.x * sn + q.y * cs));
    *(uint2*)(Ko + o) = make_uint2(f2tf(k.x * cs - k.y * sn),
                                   f2tf(k.x * sn + k.y * cs));
}

// ---------------------------------------------------------------------------
// Prep: V slice of qkv -> g_vt [b,h][d][key'] tf32, keys permuted within each
// 8-group: position p holds key ((p&3)<<1)|((p&7)>>2) (so S-fragment registers
// feed PV directly as the A operand).
// ---------------------------------------------------------------------------
__global__ __launch_bounds__(256) void vtrans(
    const float* __restrict__ qkv, unsigned* __restrict__ Vt)
{
    __shared__ float sm[64 * 68];
    const int tid = threadIdx.x;
    const int ktile = blockIdx.x, bh = blockIdx.y;
    const int b = bh >> 4, h = bh & 15;
    const float* Vp = qkv + (size_t)b * NL * ND3 + 2 * ND + h * DH;

#pragma unroll
    for (int i = 0; i < 4; i++) {
        int c = tid + i * 256;
        int key = c >> 4, d4 = (c & 15) << 2;
        float4 v = *(const float4*)(Vp + (size_t)(ktile * 64 + key) * ND3 + d4);
        *(float4*)&sm[key * 68 + d4] = v;
    }
    __syncthreads();
#pragma unroll
    for (int i = 0; i < 4; i++) {
        int c = tid + i * 256;
        int d = c >> 4, p4 = (c & 15) << 2;
        uint4 w;
        unsigned* pw = &w.x;
#pragma unroll
        for (int j = 0; j < 4; j++) {
            int p = p4 + j;
            int kl = (p & ~7) | (((p & 3) << 1) | ((p & 7) >> 2));
            pw[j] = f2tf(sm[kl * 68 + d]);
        }
        *(uint4*)(Vt + ((size_t)bh * DH + d) * NL + ktile * 64 + p4) = w;
    }
}

// ---------------------------------------------------------------------------
// TF32 flash attention, fixed-max softmax (scores are bounded; masked -> 0).
// q-tile 256 (8 warps x 32 rows), key-tile 64, cp.async double-buffered K/V,
// all MMA operands via ldmatrix, P stays in registers.
// ---------------------------------------------------------------------------
#define QT 256
#define KT 64
#define STR 68
#define SCL 0.1803368801111244f   /* 0.125 * log2(e) */

__global__ __launch_bounds__(256, 1) void attn_tf32(
    const unsigned* __restrict__ Qg, const unsigned* __restrict__ Kg,
    const unsigned* __restrict__ Vtg, const int* __restrict__ amask,
    unsigned* __restrict__ outw)
{
    extern __shared__ unsigned su[];
    unsigned* Qs = su;                       // [256][68]
    // Ks: 2 x [64][68], Vs: 2 x [64][68], msk: 2 x [64]
    const unsigned su0 = (unsigned)__cvta_generic_to_shared(su);
    const unsigned qs0 = su0;
    const unsigned ks0 = su0 + QT * STR * 4;
    const unsigned vs0 = ks0 + 2 * KT * STR * 4;
    float* msk = (float*)(su + QT * STR + 4 * KT * STR);

    const int tid = threadIdx.x;
    const int lane = tid & 31, wid = tid >> 5;
    const int g = lane >> 2, t = lane & 3;
    const int qt = (gridDim.x - 1) - blockIdx.x;   // heavy tiles first
    const int bh = blockIdx.y;
    const int b = bh >> 4, h = bh & 15;
    const int q0 = qt * QT;
    const int ktmax = 4 * qt + 3;

    const unsigned* Qp = Qg + ((size_t)bh * NL + q0) * DH;
    const unsigned* Kp = Kg + (size_t)bh * NL * DH;
    const unsigned* Vp = Vtg + (size_t)bh * DH * NL;

    auto copy_kv = [&](int kt_, int bf) {
        unsigned kd = ks0 + bf * (KT * STR * 4);
        unsigned vd = vs0 + bf * (KT * STR * 4);
        const unsigned* Ksrc = Kp + (size_t)kt_ * KT * DH;
        const unsigned* Vsrc = Vp + kt_ * KT;
#pragma unroll
        for (int i = 0; i < 4; i++) {
            int c = tid + i * 256;
            int r = c >> 4, c4 = (c & 15) << 2;
            cpa16(kd + (r * STR + c4) * 4, Ksrc + (size_t)r * DH + c4);
            cpa16(vd + (r * STR + c4) * 4, Vsrc + (size_t)r * NL + c4);
        }
        if (tid < KT)
            msk[bf * KT + tid] =
                amask[b * NL + kt_ * KT + tid] ? 0.f : -1e30f;
    };

    // prologue: Q + tile 0
#pragma unroll
    for (int i = 0; i < 16; i++) {
        int c = tid + i * 256;
        int r = c >> 4, c4 = (c & 15) << 2;
        cpa16(qs0 + (r * STR + c4) * 4, Qp + (size_t)r * DH + c4);
    }
    copy_kv(0, 0);
    CP_COMMIT();

    // fragment addresses
    unsigned qb[2];
#pragma unroll
    for (int mf = 0; mf < 2; mf++) {
        int row = wid * 32 + mf * 16 + (lane & 15);
        int col = (lane >> 4) << 2;
        qb[mf] = qs0 + (row * STR + col) * 4;
    }
    const int fr = (lane & 7) + ((lane & 16) ? 8 : 0);
    const int fc = (lane & 8) ? 4 : 0;
    unsigned kb[4], vb[4];
#pragma unroll
    for (int nfp = 0; nfp < 4; nfp++) {
        kb[nfp] = ks0 + ((nfp * 16 + fr) * STR + fc) * 4;
        vb[nfp] = vs0 + ((nfp * 16 + fr) * STR + fc) * 4;
    }
    const unsigned bufB = KT * STR * 4;

    float o[2][8][4];
#pragma unroll
    for (int mf = 0; mf < 2; mf++)
#pragma unroll
        for (int nf = 0; nf < 8; nf++)
#pragma unroll
            for (int i = 0; i < 4; i++) o[mf][nf][i] = 0.f;
    float l_acc[2][2] = {{0.f, 0.f}, {0.f, 0.f}};

    int buf = 0;
    for (int kt = 0; kt <= ktmax; kt++) {
        if (kt < ktmax) {
            copy_kv(kt + 1, buf ^ 1);
            CP_COMMIT();
            CP_WAIT1();
        } else {
            CP_WAIT0();
        }
        __syncthreads();

        const unsigned kofs = buf * bufB;
        const float* mb = msk + buf * KT;

        // ---- S = Q K^T ----
        float s[2][8][4];
#pragma unroll
        for (int mf = 0; mf < 2; mf++)
#pragma unroll
            for (int nf = 0; nf < 8; nf++)
#pragma unroll
                for (int i = 0; i < 4; i++) s[mf][nf][i] = 0.f;

#pragma unroll
        for (int kc = 0; kc < 8; kc++) {
            const unsigned kadd = kc * 32;
            unsigned a[2][4], bk[4];
            ldsm4(a[0], qb[0] + kadd);
            ldsm4(a[1], qb[1] + kadd);
#pragma unroll
            for (int nfp = 0; nfp < 4; nfp++) {
                ldsm4(bk, kb[nfp] + kofs + kadd);
                mma8(s[0][2 * nfp],     a[0], bk[0], bk[1]);
                mma8(s[1][2 * nfp],     a[1], bk[0], bk[1]);
                mma8(s[0][2 * nfp + 1], a[0], bk[2], bk[3]);
                mma8(s[1][2 * nfp + 1], a[1], bk[2], bk[3]);
            }
        }

        const bool diag = (kt * KT + KT - 1 > q0);

        // ---- fixed-max softmax: exp2(s*SCL + mask), accumulate row sums ----
#pragma unroll
        for (int mf = 0; mf < 2; mf++) {
            const int rlo = q0 + wid * 32 + mf * 16 + g;
            const int rhi = rlo + 8;
            float sum0 = 0.f, sum1 = 0.f;
#pragma unroll
            for (int nf = 0; nf < 8; nf++) {
                int c = kt * KT + nf * 8 + 2 * t;
                float mk0 = mb[nf * 8 + 2 * t];
                float mk1 = mb[nf * 8 + 2 * t + 1];
                float* sv = s[mf][nf];
                sv[0] = sv[0] * SCL + mk0;
                sv[1] = sv[1] * SCL + mk1;
                sv[2] = sv[2] * SCL + mk0;
                sv[3] = sv[3] * SCL + mk1;
                if (diag) {
                    if (c     > rlo) sv[0] = -1e30f;
                    if (c + 1 > rlo) sv[1] = -1e30f;
                    if (c     > rhi) sv[2] = -1e30f;
                    if (c + 1 > rhi) sv[3] = -1e30f;
                }
                sv[0] = ex2(sv[0]); sum0 += sv[0];
                sv[1] = ex2(sv[1]); sum0 += sv[1];
                sv[2] = ex2(sv[2]); sum1 += sv[2];
                sv[3] = ex2(sv[3]); sum1 += sv[3];
            }
            l_acc[mf][0] += sum0;
            l_acc[mf][1] += sum1;
        }

        // ---- O += P V  (P direct from registers, V via ldmatrix) ----
#pragma unroll
        for (int kc = 0; kc < 8; kc++) {
            const unsigned kadd = kc * 32;
            unsigned pa[2][4], bv[4];
#pragma unroll
            for (int mf = 0; mf < 2; mf++) {
                pa[mf][0] = f2tf(s[mf][kc][0]);
                pa[mf][1] = f2tf(s[mf][kc][2]);
                pa[mf][2] = f2tf(s[mf][kc][1]);
                pa[mf][3] = f2tf(s[mf][kc][3]);
            }
#pragma unroll
            for (int nfp = 0; nfp < 4; nfp++) {
                ldsm4(bv, vb[nfp] + kofs + kadd);
                mma8(o[0][2 * nfp],     pa[0], bv[0], bv[1]);
                mma8(o[1][2 * nfp],     pa[1], bv[0], bv[1]);
                mma8(o[0][2 * nfp + 1], pa[0], bv[2], bv[3]);
                mma8(o[1][2 * nfp + 1], pa[1], bv[2], bv[3]);
            }
        }
        __syncthreads();
        buf ^= 1;
    }

    // ---- finalize: reduce l across the 4 t-lanes, write tf32 out ----
#pragma unroll
    for (int mf = 0; mf < 2; mf++) {
        float s0 = l_acc[mf][0], s1 = l_acc[mf][1];
        s0 += __shfl_xor_sync(0xffffffffu, s0, 1);
        s0 += __shfl_xor_sync(0xffffffffu, s0, 2);
        s1 += __shfl_xor_sync(0xffffffffu, s1, 1);
        s1 += __shfl_xor_sync(0xffffffffu, s1, 2);
        float inv0 = 1.f / s0, inv1 = 1.f / s1;
        int rlo = q0 + wid * 32 + mf * 16 + g;
        unsigned* op = outw + ((size_t)b * NL + rlo) * ND + h * DH;
#pragma unroll
        for (int nf = 0; nf < 8; nf++) {
            int col = nf * 8 + 2 * t;
            *(uint2*)(op + col) =
                make_uint2(f2tf(o[mf][nf][0] * inv0),
                           f2tf(o[mf][nf][1] * inv0));
            *(uint2*)(op + (size_t)8 * ND + col) =
                make_uint2(f2tf(o[mf][nf][2] * inv1),
                           f2tf(o[mf][nf][3] * inv1));
        }
    }
}

// ---------------------------------------------------------------------------
extern "C" void kernel_launch(void* const* d_in, const int* in_sizes, int n_in,
                              void* d_out, int out_size)
{
    const float* x     = (const float*)d_in[0];
    const float* Wqkv  = (const float*)d_in[1];
    const float* bqkv  = (const float*)d_in[2];
    const float* Wproj = (const float*)d_in[3];
    const float* bproj = (const float*)d_in[4];
    const int*   amask = (const int*)d_in[5];
    float* out = (float*)d_out;

    float *qkv;
    unsigned *xt, *wqkvt, *wprojt, *q, *k, *vt, *attn;
    cudaGetSymbolAddress((void**)&qkv,    g_qkv);
    cudaGetSymbolAddress((void**)&xt,     g_xt);
    cudaGetSymbolAddress((void**)&wqkvt,  g_wqkvt);
    cudaGetSymbolAddress((void**)&wprojt, g_wprojt);
    cudaGetSymbolAddress((void**)&q,      g_q);
    cudaGetSymbolAddress((void**)&k,      g_k);
    cudaGetSymbolAddress((void**)&vt,     g_vt);
    cudaGetSymbolAddress((void**)&attn,   g_attn);

    const int gemm_smem = 2 * 2 * 4608 * 4;   // 73728 B
    cudaFuncSetAttribute(gemm_tf32,
                         cudaFuncAttributeMaxDynamicSharedMemorySize,
                         gemm_smem);
    const int attn_smem = (QT * STR + 4 * KT * STR + 2 * KT) * 4;
    cudaFuncSetAttribute(attn_tf32,
                         cudaFuncAttributeMaxDynamicSharedMemorySize,
                         attn_smem);

    // Prep: convert x, transpose weights
    int n4 = (NB * NL * ND) / 4;
    conv_tf32<<<(n4 + 255) / 256, 256>>>(x, xt, n4);
    wtrans<<<dim3(ND3 / 32, ND / 32), 256>>>(Wqkv, wqkvt, ND, ND3);
    wtrans<<<dim3(ND / 32, ND / 32), 256>>>(Wproj, wprojt, ND, ND);

    // 1) QKV projection
    gemm_tf32<<<dim3(ND3 / 128, (NB * NL) / 128), 256, gemm_smem>>>(
        xt, wqkvt, bqkv, qkv, NB * NL, ND3, ND);

    // 2) RoPE + V transpose
    int total = NB * NL * NH * (DH / 2);
    rope_kernel<<<(total + 255) / 256, 256>>>(qkv, q, k);
    vtrans<<<dim3(NL / 64, NB * NH), 256>>>(qkv, vt);

    // 3) Attention
    attn_tf32<<<dim3(NL / QT, NB * NH), 256, attn_smem>>>(
        q, k, vt, amask, attn);

    // 4) Output projection
    gemm_tf32<<<dim3(ND / 128, (NB * NL) / 128), 256, gemm_smem>>>(
        attn, wprojt, bproj, out, NB * NL, ND, ND);
}

// round 6
// speedup vs baseline: 2.3429x; 2.3429x over previous
#include <cuda_runtime.h>
#include <cuda_fp16.h>
#include <math.h>

#define NB 4
#define NL 2048
#define ND 1024
#define NH 16
#define DH 64
#define ND3 (3*ND)

// Scratch (allocation-free: __device__ globals)
__device__ __half g_xh   [(size_t)NB*NL*ND];     // x fp16
__device__ __half g_wqkvh[(size_t)ND3*ND];       // W_qkv^T fp16 [N][K]
__device__ __half g_wprojh[(size_t)ND*ND];       // W_proj^T fp16 [N][K]
__device__ __half g_qkvh [(size_t)NB*NL*ND3];    // qkv fp16 [b,l,3ND]
__device__ __half g_qh   [(size_t)NB*NH*NL*DH];  // roped Q fp16 [b,h,l,d]
__device__ __half g_kh   [(size_t)NB*NH*NL*DH];  // roped K fp16 [b,h,l,d]
__device__ __half g_vh   [(size_t)NB*NH*NL*DH];  // V fp16 [b,h,l,d]
__device__ __half g_attnh[(size_t)NB*NL*ND];     // attn out fp16 [b,l,nd]

__device__ __forceinline__ unsigned pack2(float a, float b) {
    __half2 h = __floats2half2_rn(a, b);
    return *reinterpret_cast<unsigned*>(&h);
}
__device__ __forceinline__ float ex2(float x) {
    float y;
    asm("ex2.approx.f32 %0, %1;" : "=f"(y) : "f"(x));
    return y;
}
__device__ __forceinline__ void mma16(float* d, const unsigned* a,
                                      unsigned b0, unsigned b1) {
    asm volatile(
        "mma.sync.aligned.m16n8k16.row.col.f32.f16.f16.f32 "
        "{%0,%1,%2,%3}, {%4,%5,%6,%7}, {%8,%9}, {%0,%1,%2,%3};"
        : "+f"(d[0]), "+f"(d[1]), "+f"(d[2]), "+f"(d[3])
        : "r"(a[0]), "r"(a[1]), "r"(a[2]), "r"(a[3]), "r"(b0), "r"(b1));
}
__device__ __forceinline__ void ldsm4(unsigned* r, unsigned addr) {
    asm volatile(
        "ldmatrix.sync.aligned.m8n8.x4.shared.b16 {%0,%1,%2,%3}, [%4];"
        : "=r"(r[0]), "=r"(r[1]), "=r"(r[2]), "=r"(r[3]) : "r"(addr));
}
__device__ __forceinline__ void ldsm4t(unsigned* r, unsigned addr) {
    asm volatile(
        "ldmatrix.sync.aligned.m8n8.x4.trans.shared.b16 {%0,%1,%2,%3}, [%4];"
        : "=r"(r[0]), "=r"(r[1]), "=r"(r[2]), "=r"(r[3]) : "r"(addr));
}
__device__ __forceinline__ void cpa16(unsigned dst, const void* src) {
    asm volatile("cp.async.cg.shared.global [%0], [%1], 16;"
                 :: "r"(dst), "l"(src));
}
#define CP_COMMIT() asm volatile("cp.async.commit_group;")
#define CP_WAIT1()  asm volatile("cp.async.wait_group 1;")
#define CP_WAIT0()  asm volatile("cp.async.wait_group 0;")

// ---------------------------------------------------------------------------
// Prep: fp32 -> fp16 bulk convert (8 elems/thread)
// ---------------------------------------------------------------------------
__global__ void conv_h(const float* __restrict__ src,
                       __half* __restrict__ dst, int n8)
{
    int i = blockIdx.x * blockDim.x + threadIdx.x;
    if (i < n8) {
        float4 a = ((const float4*)src)[2 * i];
        float4 b = ((const float4*)src)[2 * i + 1];
        uint4 w;
        w.x = pack2(a.x, a.y); w.y = pack2(a.z, a.w);
        w.z = pack2(b.x, b.y); w.w = pack2(b.z, b.w);
        ((uint4*)dst)[i] = w;
    }
}

// ---------------------------------------------------------------------------
// Prep: W [K][N] fp32 -> Wt [N][K] fp16
// ---------------------------------------------------------------------------
__global__ __launch_bounds__(256) void wtrans_h(
    const float* __restrict__ W, __half* __restrict__ Wt, int K, int N)
{
    __shared__ float sm[32][33];
    int tx = threadIdx.x & 31, ty = threadIdx.x >> 5;
    int n0 = blockIdx.x * 32, k0 = blockIdx.y * 32;
#pragma unroll
    for (int j = 0; j < 4; j++)
        sm[ty + 8 * j][tx] = W[(size_t)(k0 + ty + 8 * j) * N + n0 + tx];
    __syncthreads();
#pragma unroll
    for (int j = 0; j < 4; j++)
        Wt[(size_t)(n0 + ty + 8 * j) * K + k0 + tx] =
            __float2half(sm[tx][ty + 8 * j]);
}

// ---------------------------------------------------------------------------
// FP16 GEMM + bias: C[M][N] = A[M][K] @ Bt[N][K]^T + bias[N].
// CTA 128x128, BK=32, LDG reg-prefetch + double-buffered SMEM (1 sync/tile).
// 8 warps (4m x 2n), warp tile 32x64, m16n8k16. 2 CTAs/SM.
// outfp16: 1 -> C is __half, 0 -> C is float.
// ---------------------------------------------------------------------------
__global__ __launch_bounds__(256, 2) void gemm_h(
    const __half* __restrict__ A, const __half* __restrict__ Bt,
    const float* __restrict__ bias, void* __restrict__ Cv,
    int M, int N, int K, int outfp16)
{
    __shared__ __half sh[2][2][128 * 40];   // [buf][A/B][row*40+k]
    const int tid = threadIdx.x;
    const int lane = tid & 31, wid = tid >> 5;
    const int wm = wid >> 1, wn = wid & 1;
    const int g = lane >> 2, t = lane & 3;

    const __half* Ag = A + (size_t)blockIdx.y * 128 * K;
    const __half* Bg = Bt + (size_t)blockIdx.x * 128 * K;

    float acc[2][8][4];
#pragma unroll
    for (int mf = 0; mf < 2; mf++)
#pragma unroll
        for (int nf = 0; nf < 8; nf++)
#pragma unroll
            for (int i = 0; i < 4; i++) acc[mf][nf][i] = 0.f;

    const int crow = tid >> 2, coff = (tid & 3) * 8;

    uint4 ar[2], br[2];
    {
        ar[0] = *(const uint4*)(Ag + (size_t)crow * K + coff);
        ar[1] = *(const uint4*)(Ag + (size_t)(crow + 64) * K + coff);
        br[0] = *(const uint4*)(Bg + (size_t)crow * K + coff);
        br[1] = *(const uint4*)(Bg + (size_t)(crow + 64) * K + coff);
    }

    // fragment lane geometry
    const int arow_l = ((lane >> 3) & 1) * 8 + (lane & 7);
    const int akoff_l = (lane >> 4) * 8;
    const int brow_l = ((lane >> 4) & 1) * 8 + (lane & 7);
    const int bkoff_l = ((lane >> 3) & 1) * 8;

    const int nt = K / 32;
    for (int tile = 0; tile < nt; tile++) {
        const int buf = tile & 1;
        {
            __half* as = sh[buf][0];
            __half* bs = sh[buf][1];
            *(uint4*)(as + crow * 40 + coff) = ar[0];
            *(uint4*)(as + (crow + 64) * 40 + coff) = ar[1];
            *(uint4*)(bs + crow * 40 + coff) = br[0];
            *(uint4*)(bs + (crow + 64) * 40 + coff) = br[1];
        }
        if (tile + 1 < nt) {
            const __half* An = Ag + (tile + 1) * 32;
            const __half* Bn = Bg + (tile + 1) * 32;
            ar[0] = *(const uint4*)(An + (size_t)crow * K + coff);
            ar[1] = *(const uint4*)(An + (size_t)(crow + 64) * K + coff);
            br[0] = *(const uint4*)(Bn + (size_t)crow * K + coff);
            br[1] = *(const uint4*)(Bn + (size_t)(crow + 64) * K + coff);
        }
        __syncthreads();

        const unsigned as0 = (unsigned)__cvta_generic_to_shared(sh[buf][0]);
        const unsigned bs0 = (unsigned)__cvta_generic_to_shared(sh[buf][1]);
#pragma unroll
        for (int kc = 0; kc < 2; kc++) {
            unsigned a[2][4];
            ldsm4(a[0], as0 + ((wm * 32 + arow_l) * 40 + kc * 16 + akoff_l) * 2);
            ldsm4(a[1], as0 + ((wm * 32 + 16 + arow_l) * 40 + kc * 16 + akoff_l) * 2);
#pragma unroll
            for (int nfp = 0; nfp < 4; nfp++) {
                unsigned bk[4];
                ldsm4(bk, bs0 + ((wn * 64 + nfp * 16 + brow_l) * 40
                                 + kc * 16 + bkoff_l) * 2);
                mma16(acc[0][2 * nfp],     a[0], bk[0], bk[1]);
                mma16(acc[1][2 * nfp],     a[1], bk[0], bk[1]);
                mma16(acc[0][2 * nfp + 1], a[0], bk[2], bk[3]);
                mma16(acc[1][2 * nfp + 1], a[1], bk[2], bk[3]);
            }
        }
    }

#pragma unroll
    for (int mf = 0; mf < 2; mf++) {
        int row = blockIdx.y * 128 + wm * 32 + mf * 16 + g;
#pragma unroll
        for (int nf = 0; nf < 8; nf++) {
            int col = blockIdx.x * 128 + wn * 64 + nf * 8 + 2 * t;
            float b0 = bias[col], b1 = bias[col + 1];
            if (outfp16) {
                __half* C = (__half*)Cv;
                *(unsigned*)(C + (size_t)row * N + col) =
                    pack2(acc[mf][nf][0] + b0, acc[mf][nf][1] + b1);
                *(unsigned*)(C + (size_t)(row + 8) * N + col) =
                    pack2(acc[mf][nf][2] + b0, acc[mf][nf][3] + b1);
            } else {
                float* C = (float*)Cv;
                *(float2*)(C + (size_t)row * N + col) =
                    make_float2(acc[mf][nf][0] + b0, acc[mf][nf][1] + b1);
                *(float2*)(C + (size_t)(row + 8) * N + col) =
                    make_float2(acc[mf][nf][2] + b0, acc[mf][nf][3] + b1);
            }
        }
    }
}

// ---------------------------------------------------------------------------
// Split + RoPE: qkvh fp16 [b,l,3ND] -> roped Q,K and plain V in [b,h,l,d] fp16
// ---------------------------------------------------------------------------
__global__ void split_rope(const __half* __restrict__ qkvh,
                           __half* __restrict__ qh, __half* __restrict__ kh,
                           __half* __restrict__ vh)
{
    int idx = blockIdx.x * blockDim.x + threadIdx.x;
    const int total = NB * NL * NH * (DH / 2);
    if (idx >= total) return;
    int i = idx & 31;
    int h = (idx >> 5) & 15;
    int l = (idx >> 9) & (NL - 1);
    int b = idx >> 20;

    float inv = powf(10000.0f, -(float)(2 * i) / (float)DH);
    float ang = (float)l * inv;
    float sn, cs;
    sincosf(ang, &sn, &cs);

    const __half* base = qkvh + (size_t)(b * NL + l) * ND3 + h * DH + 2 * i;
    float2 q = __half22float2(*(const __half2*)(base));
    float2 k = __half22float2(*(const __half2*)(base + ND));
    unsigned vraw = *(const unsigned*)(base + 2 * ND);

    size_t o = ((size_t)(b * NH + h) * NL + l) * DH + 2 * i;
    *(unsigned*)(qh + o) = pack2(q.x * cs - q.y * sn, q.x * sn + q.y * cs);
    *(unsigned*)(kh + o) = pack2(k.x * cs - k.y * sn, k.x * sn + k.y * cs);
    *(unsigned*)(vh + o) = vraw;
}

// ---------------------------------------------------------------------------
// FP16 flash attention, fixed-max softmax. q-tile 256 (8 warps x 32 rows),
// key-tile 64, cp.async double-buffered K/V, all operands via ldmatrix
// (V via ldmatrix.trans), P fed to PV directly from S fragments.
// ---------------------------------------------------------------------------
#define QT 256
#define KT 64
#define STR 72   /* halfs per row */
#define SCL 0.1803368801111244f   /* 0.125 * log2(e) */

__global__ __launch_bounds__(256, 1) void attn_h(
    const __half* __restrict__ Qg, const __half* __restrict__ Kg,
    const __half* __restrict__ Vg, const int* __restrict__ amask,
    __half* __restrict__ outh)
{
    extern __shared__ __half sa[];
    // Qs [256][72], Ks 2x[64][72], Vs 2x[64][72], msk 2x[64] floats
    const unsigned qs0 = (unsigned)__cvta_generic_to_shared(sa);
    const unsigned ks0 = qs0 + QT * STR * 2;
    const unsigned vs0 = ks0 + 2 * KT * STR * 2;
    float* msk = (float*)(sa + QT * STR + 4 * KT * STR);

    const int tid = threadIdx.x;
    const int lane = tid & 31, wid = tid >> 5;
    const int g = lane >> 2, t = lane & 3;
    const int qt = (gridDim.x - 1) - blockIdx.x;   // heavy tiles first
    const int bh = blockIdx.y;
    const int b = bh >> 4, h = bh & 15;
    const int q0 = qt * QT;
    const int ktmax = 4 * qt + 3;

    const __half* Qp = Qg + ((size_t)bh * NL + q0) * DH;
    const __half* Kp = Kg + (size_t)bh * NL * DH;
    const __half* Vp = Vg + (size_t)bh * NL * DH;

    auto copy_kv = [&](int kt_, int bf) {
        unsigned kd = ks0 + bf * (KT * STR * 2);
        unsigned vd = vs0 + bf * (KT * STR * 2);
        const __half* Ksrc = Kp + (size_t)kt_ * KT * DH;
        const __half* Vsrc = Vp + (size_t)kt_ * KT * DH;
#pragma unroll
        for (int i = 0; i < 2; i++) {
            int c = tid + i * 256;
            int r = c >> 3, o8 = (c & 7) * 8;
            cpa16(kd + (r * STR + o8) * 2, Ksrc + r * DH + o8);
            cpa16(vd + (r * STR + o8) * 2, Vsrc + r * DH + o8);
        }
        if (tid < KT)
            msk[bf * KT + tid] =
                amask[b * NL + kt_ * KT + tid] ? 0.f : -1e30f;
    };

    // prologue: Q + tile 0
#pragma unroll
    for (int i = 0; i < 8; i++) {
        int c = tid + i * 256;
        int r = c >> 3, o8 = (c & 7) * 8;
        cpa16(qs0 + (r * STR + o8) * 2, Qp + (size_t)r * DH + o8);
    }
    copy_kv(0, 0);
    CP_COMMIT();

    // fragment lane geometry
    const int arow_l = ((lane >> 3) & 1) * 8 + (lane & 7);  // A (Q) rows
    const int akoff_l = (lane >> 4) * 8;
    const int krow_l = ((lane >> 4) & 1) * 8 + (lane & 7);  // K (B) rows
    const int kkoff_l = ((lane >> 3) & 1) * 8;
    const int vkey_l = ((lane >> 4) & 1) * 8 + (lane & 7);  // V (trans) rows
    const int vdoff_l = ((lane >> 3) & 1) * 8;

    unsigned qb[2];
#pragma unroll
    for (int mf = 0; mf < 2; mf++)
        qb[mf] = qs0 + ((wid * 32 + mf * 16 + arow_l) * STR + akoff_l) * 2;
    unsigned kbb[4], vbb[4];
#pragma unroll
    for (int j = 0; j < 4; j++) {
        kbb[j] = ks0 + ((j * 16 + krow_l) * STR + kkoff_l) * 2;
        vbb[j] = vs0 + (vkey_l * STR + j * 16 + vdoff_l) * 2;
    }
    const unsigned bufB = KT * STR * 2;

    float o[2][8][4];
#pragma unroll
    for (int mf = 0; mf < 2; mf++)
#pragma unroll
        for (int nf = 0; nf < 8; nf++)
#pragma unroll
            for (int i = 0; i < 4; i++) o[mf][nf][i] = 0.f;
    float l_acc[2][2] = {{0.f, 0.f}, {0.f, 0.f}};

    int buf = 0;
    for (int kt = 0; kt <= ktmax; kt++) {
        if (kt < ktmax) {
            copy_kv(kt + 1, buf ^ 1);
            CP_COMMIT();
            CP_WAIT1();
        } else {
            CP_WAIT0();
        }
        __syncthreads();

        const unsigned kofs = buf * bufB;
        const float* mb = msk + buf * KT;

        // ---- S = Q K^T ----
        float s[2][8][4];
#pragma unroll
        for (int mf = 0; mf < 2; mf++)
#pragma unroll
            for (int nf = 0; nf < 8; nf++)
#pragma unroll
                for (int i = 0; i < 4; i++) s[mf][nf][i] = 0.f;

#pragma unroll
        for (int kc = 0; kc < 4; kc++) {
            unsigned a[2][4], bk[4];
            ldsm4(a[0], qb[0] + kc * 32);
            ldsm4(a[1], qb[1] + kc * 32);
#pragma unroll
            for (int nfp = 0; nfp < 4; nfp++) {
                ldsm4(bk, kbb[nfp] + kofs + kc * 32);
                mma16(s[0][2 * nfp],     a[0], bk[0], bk[1]);
                mma16(s[1][2 * nfp],     a[1], bk[0], bk[1]);
                mma16(s[0][2 * nfp + 1], a[0], bk[2], bk[3]);
                mma16(s[1][2 * nfp + 1], a[1], bk[2], bk[3]);
            }
        }

        const bool diag = (kt * KT + KT - 1 > q0);

        // ---- fixed-max softmax: exp2(s*SCL + mask) ----
#pragma unroll
        for (int mf = 0; mf < 2; mf++) {
            const int rlo = q0 + wid * 32 + mf * 16 + g;
            const int rhi = rlo + 8;
            float sum0 = 0.f, sum1 = 0.f;
#pragma unroll
            for (int nf = 0; nf < 8; nf++) {
                int c = kt * KT + nf * 8 + 2 * t;
                float mk0 = mb[nf * 8 + 2 * t];
                float mk1 = mb[nf * 8 + 2 * t + 1];
                float* sv = s[mf][nf];
                sv[0] = sv[0] * SCL + mk0;
                sv[1] = sv[1] * SCL + mk1;
                sv[2] = sv[2] * SCL + mk0;
                sv[3] = sv[3] * SCL + mk1;
                if (diag) {
                    if (c     > rlo) sv[0] = -1e30f;
                    if (c + 1 > rlo) sv[1] = -1e30f;
                    if (c     > rhi) sv[2] = -1e30f;
                    if (c + 1 > rhi) sv[3] = -1e30f;
                }
                sv[0] = ex2(sv[0]); sum0 += sv[0];
                sv[1] = ex2(sv[1]); sum0 += sv[1];
                sv[2] = ex2(sv[2]); sum1 += sv[2];
                sv[3] = ex2(sv[3]); sum1 += sv[3];
            }
            l_acc[mf][0] += sum0;
            l_acc[mf][1] += sum1;
        }

        // ---- O += P V  (P packed from S regs; V via ldmatrix.trans) ----
#pragma unroll
        for (int kc = 0; kc < 4; kc++) {
            unsigned pa[2][4];
#pragma unroll
            for (int mf = 0; mf < 2; mf++) {
                pa[mf][0] = pack2(s[mf][2 * kc][0],     s[mf][2 * kc][1]);
                pa[mf][1] = pack2(s[mf][2 * kc][2],     s[mf][2 * kc][3]);
                pa[mf][2] = pack2(s[mf][2 * kc + 1][0], s[mf][2 * kc + 1][1]);
                pa[mf][3] = pack2(s[mf][2 * kc + 1][2], s[mf][2 * kc + 1][3]);
            }
#pragma unroll
            for (int db = 0; db < 4; db++) {
                unsigned bv[4];
                ldsm4t(bv, vbb[db] + kofs + kc * (16 * STR * 2));
                mma16(o[0][2 * db],     pa[0], bv[0], bv[2]);
                mma16(o[1][2 * db],     pa[1], bv[0], bv[2]);
                mma16(o[0][2 * db + 1], pa[0], bv[1], bv[3]);
                mma16(o[1][2 * db + 1], pa[1], bv[1], bv[3]);
            }
        }
        __syncthreads();
        buf ^= 1;
    }

    // ---- finalize: reduce l over t-lanes, write fp16 out [b,l,h*64+d] ----
#pragma unroll
    for (int mf = 0; mf < 2; mf++) {
        float s0 = l_acc[mf][0], s1 = l_acc[mf][1];
        s0 += __shfl_xor_sync(0xffffffffu, s0, 1);
        s0 += __shfl_xor_sync(0xffffffffu, s0, 2);
        s1 += __shfl_xor_sync(0xffffffffu, s1, 1);
        s1 += __shfl_xor_sync(0xffffffffu, s1, 2);
        float inv0 = 1.f / s0, inv1 = 1.f / s1;
        int rlo = q0 + wid * 32 + mf * 16 + g;
        __half* op = outh + ((size_t)b * NL + rlo) * ND + h * DH;
#pragma unroll
        for (int nf = 0; nf < 8; nf++) {
            int col = nf * 8 + 2 * t;
            *(unsigned*)(op + col) =
                pack2(o[mf][nf][0] * inv0, o[mf][nf][1] * inv0);
            *(unsigned*)(op + (size_t)8 * ND + col) =
                pack2(o[mf][nf][2] * inv1, o[mf][nf][3] * inv1);
        }
    }
}

// ---------------------------------------------------------------------------
extern "C" void kernel_launch(void* const* d_in, const int* in_sizes, int n_in,
                              void* d_out, int out_size)
{
    const float* x     = (const float*)d_in[0];
    const float* Wqkv  = (const float*)d_in[1];
    const float* bqkv  = (const float*)d_in[2];
    const float* Wproj = (const float*)d_in[3];
    const float* bproj = (const float*)d_in[4];
    const int*   amask = (const int*)d_in[5];
    float* out = (float*)d_out;

    __half *xh, *wqkvh, *wprojh, *qkvh, *qh, *kh, *vh, *attnh;
    cudaGetSymbolAddress((void**)&xh,     g_xh);
    cudaGetSymbolAddress((void**)&wqkvh,  g_wqkvh);
    cudaGetSymbolAddress((void**)&wprojh, g_wprojh);
    cudaGetSymbolAddress((void**)&qkvh,   g_qkvh);
    cudaGetSymbolAddress((void**)&qh,     g_qh);
    cudaGetSymbolAddress((void**)&kh,     g_kh);
    cudaGetSymbolAddress((void**)&vh,     g_vh);
    cudaGetSymbolAddress((void**)&attnh,  g_attnh);

    const int attn_smem = (QT * STR + 4 * KT * STR) * 2 + 2 * KT * 4;
    cudaFuncSetAttribute(attn_h,
                         cudaFuncAttributeMaxDynamicSharedMemorySize,
                         attn_smem);

    // Prep: convert x, transpose+convert weights
    int n8 = (NB * NL * ND) / 8;
    conv_h<<<(n8 + 255) / 256, 256>>>(x, xh, n8);
    wtrans_h<<<dim3(ND3 / 32, ND / 32), 256>>>(Wqkv, wqkvh, ND, ND3);
    wtrans_h<<<dim3(ND / 32, ND / 32), 256>>>(Wproj, wprojh, ND, ND);

    // 1) QKV projection -> fp16
    gemm_h<<<dim3(ND3 / 128, (NB * NL) / 128), 256>>>(
        xh, wqkvh, bqkv, qkvh, NB * NL, ND3, ND, 1);

    // 2) Split + RoPE -> Q,K,V in [b,h,l,d] fp16
    int total = NB * NL * NH * (DH / 2);
    split_rope<<<(total + 255) / 256, 256>>>(qkvh, qh, kh, vh);

    // 3) Attention -> fp16 [b,l,nd]
    attn_h<<<dim3(NL / QT, NB * NH), 256, attn_smem>>>(
        qh, kh, vh, amask, attnh);

    // 4) Output projection -> fp32
    gemm_h<<<dim3(ND / 128, (NB * NL) / 128), 256>>>(
        attnh, wprojh, bproj, out, NB * NL, ND, ND, 0);
}

// round 11
// speedup vs baseline: 2.4166x; 1.0315x over previous
#include <cuda_runtime.h>
#include <cuda_fp16.h>
#include <math.h>

#define NB 4
#define NL 2048
#define ND 1024
#define NH 16
#define DH 64
#define ND3 (3*ND)

// Scratch (allocation-free: __device__ globals)
__device__ __half g_xh    [(size_t)NB*NL*ND];    // x fp16
__device__ __half g_wqkvh [(size_t)ND3*ND];      // W_qkv^T fp16 [N][K]
__device__ __half g_wprojh[(size_t)ND*ND];       // W_proj^T fp16 [N][K]
__device__ __half g_qh    [(size_t)NB*NH*NL*DH]; // roped Q fp16 [b,h,l,d]
__device__ __half g_kh    [(size_t)NB*NH*NL*DH]; // roped K fp16 [b,h,l,d]
__device__ __half g_vh    [(size_t)NB*NH*NL*DH]; // V fp16 [b,h,l,d]
__device__ __half g_attnh [(size_t)NB*NL*ND];    // attn out fp16 [b,l,nd]

__device__ __forceinline__ unsigned pack2(float a, float b) {
    __half2 h = __floats2half2_rn(a, b);
    return *reinterpret_cast<unsigned*>(&h);
}
__device__ __forceinline__ float ex2(float x) {
    float y;
    asm("ex2.approx.f32 %0, %1;" : "=f"(y) : "f"(x));
    return y;
}
__device__ __forceinline__ void mma16(float* d, const unsigned* a,
                                      unsigned b0, unsigned b1) {
    asm volatile(
        "mma.sync.aligned.m16n8k16.row.col.f32.f16.f16.f32 "
        "{%0,%1,%2,%3}, {%4,%5,%6,%7}, {%8,%9}, {%0,%1,%2,%3};"
        : "+f"(d[0]), "+f"(d[1]), "+f"(d[2]), "+f"(d[3])
        : "r"(a[0]), "r"(a[1]), "r"(a[2]), "r"(a[3]), "r"(b0), "r"(b1));
}
__device__ __forceinline__ void ldsm4(unsigned* r, unsigned addr) {
    asm volatile(
        "ldmatrix.sync.aligned.m8n8.x4.shared.b16 {%0,%1,%2,%3}, [%4];"
        : "=r"(r[0]), "=r"(r[1]), "=r"(r[2]), "=r"(r[3]) : "r"(addr));
}
__device__ __forceinline__ void ldsm4t(unsigned* r, unsigned addr) {
    asm volatile(
        "ldmatrix.sync.aligned.m8n8.x4.trans.shared.b16 {%0,%1,%2,%3}, [%4];"
        : "=r"(r[0]), "=r"(r[1]), "=r"(r[2]), "=r"(r[3]) : "r"(addr));
}
__device__ __forceinline__ void cpa16(unsigned dst, const void* src) {
    asm volatile("cp.async.cg.shared.global [%0], [%1], 16;"
                 :: "r"(dst), "l"(src));
}
#define CP_COMMIT() asm volatile("cp.async.commit_group;")
#define CP_WAIT1()  asm volatile("cp.async.wait_group 1;")
#define CP_WAIT0()  asm volatile("cp.async.wait_group 0;")

// ---------------------------------------------------------------------------
// Prep: fp32 -> fp16 bulk convert
// ---------------------------------------------------------------------------
__global__ void conv_h(const float* __restrict__ src,
                       __half* __restrict__ dst, int n8)
{
    int i = blockIdx.x * blockDim.x + threadIdx.x;
    if (i < n8) {
        float4 a = ((const float4*)src)[2 * i];
        float4 b = ((const float4*)src)[2 * i + 1];
        uint4 w;
        w.x = pack2(a.x, a.y); w.y = pack2(a.z, a.w);
        w.z = pack2(b.x, b.y); w.w = pack2(b.z, b.w);
        ((uint4*)dst)[i] = w;
    }
}

// ---------------------------------------------------------------------------
// Prep: W [K][N] fp32 -> Wt [N][K] fp16
// ---------------------------------------------------------------------------
__global__ __launch_bounds__(256) void wtrans_h(
    const float* __restrict__ W, __half* __restrict__ Wt, int K, int N)
{
    __shared__ float sm[32][33];
    int tx = threadIdx.x & 31, ty = threadIdx.x >> 5;
    int n0 = blockIdx.x * 32, k0 = blockIdx.y * 32;
#pragma unroll
    for (int j = 0; j < 4; j++)
        sm[ty + 8 * j][tx] = W[(size_t)(k0 + ty + 8 * j) * N + n0 + tx];
    __syncthreads();
#pragma unroll
    for (int j = 0; j < 4; j++)
        Wt[(size_t)(n0 + ty + 8 * j) * K + k0 + tx] =
            __float2half(sm[tx][ty + 8 * j]);
}

// ---------------------------------------------------------------------------
// FP16 GEMM: C[M][N] = A[M][K] @ Bt[N][K]^T + bias[N].
// CTA 128x128, BK=32, LDG reg-prefetch + double-buffered SMEM.
// 8 warps (4m x 2n), warp tile 32x64, m16n8k16. 2 CTAs/SM.
// mode 0: C fp32 [M][N].  mode 1: fused QKV epilogue -> rope-split into
//         qh/kh/vh ([b,h,l,d], fp16), rope applied to q/k sections.
// ---------------------------------------------------------------------------
__global__ __launch_bounds__(256, 2) void gemm_h(
    const __half* __restrict__ A, const __half* __restrict__ Bt,
    const float* __restrict__ bias, float* __restrict__ Cf,
    __half* __restrict__ qh, __half* __restrict__ kh,
    __half* __restrict__ vh,
    int M, int N, int K, int mode)
{
    __shared__ __half sh[2][2][128 * 40];   // [buf][A/B][row*40+k]
    const int tid = threadIdx.x;
    const int lane = tid & 31, wid = tid >> 5;
    const int wm = wid >> 1, wn = wid & 1;
    const int g = lane >> 2, t = lane & 3;

    const __half* Ag = A + (size_t)blockIdx.y * 128 * K;
    const __half* Bg = Bt + (size_t)blockIdx.x * 128 * K;

    float acc[2][8][4];
#pragma unroll
    for (int mf = 0; mf < 2; mf++)
#pragma unroll
        for (int nf = 0; nf < 8; nf++)
#pragma unroll
            for (int i = 0; i < 4; i++) acc[mf][nf][i] = 0.f;

    const int crow = tid >> 2, coff = (tid & 3) * 8;

    uint4 ar[2], br[2];
    ar[0] = *(const uint4*)(Ag + (size_t)crow * K + coff);
    ar[1] = *(const uint4*)(Ag + (size_t)(crow + 64) * K + coff);
    br[0] = *(const uint4*)(Bg + (size_t)crow * K + coff);
    br[1] = *(const uint4*)(Bg + (size_t)(crow + 64) * K + coff);

    const int arow_l = ((lane >> 3) & 1) * 8 + (lane & 7);
    const int akoff_l = (lane >> 4) * 8;
    const int brow_l = ((lane >> 4) & 1) * 8 + (lane & 7);
    const int bkoff_l = ((lane >> 3) & 1) * 8;

    const int nt = K / 32;
    for (int tile = 0; tile < nt; tile++) {
        const int buf = tile & 1;
        {
            __half* as = sh[buf][0];
            __half* bs = sh[buf][1];
            *(uint4*)(as + crow * 40 + coff) = ar[0];
            *(uint4*)(as + (crow + 64) * 40 + coff) = ar[1];
            *(uint4*)(bs + crow * 40 + coff) = br[0];
            *(uint4*)(bs + (crow + 64) * 40 + coff) = br[1];
        }
        if (tile + 1 < nt) {
            const __half* An = Ag + (tile + 1) * 32;
            const __half* Bn = Bg + (tile + 1) * 32;
            ar[0] = *(const uint4*)(An + (size_t)crow * K + coff);
            ar[1] = *(const uint4*)(An + (size_t)(crow + 64) * K + coff);
            br[0] = *(const uint4*)(Bn + (size_t)crow * K + coff);
            br[1] = *(const uint4*)(Bn + (size_t)(crow + 64) * K + coff);
        }
        __syncthreads();

        const unsigned as0 = (unsigned)__cvta_generic_to_shared(sh[buf][0]);
        const unsigned bs0 = (unsigned)__cvta_generic_to_shared(sh[buf][1]);
#pragma unroll
        for (int kc = 0; kc < 2; kc++) {
            unsigned a[2][4];
            ldsm4(a[0], as0 + ((wm * 32 + arow_l) * 40 + kc * 16 + akoff_l) * 2);
            ldsm4(a[1], as0 + ((wm * 32 + 16 + arow_l) * 40 + kc * 16 + akoff_l) * 2);
#pragma unroll
            for (int nfp = 0; nfp < 4; nfp++) {
                unsigned bk[4];
                ldsm4(bk, bs0 + ((wn * 64 + nfp * 16 + brow_l) * 40
                                 + kc * 16 + bkoff_l) * 2);
                mma16(acc[0][2 * nfp],     a[0], bk[0], bk[1]);
                mma16(acc[1][2 * nfp],     a[1], bk[0], bk[1]);
                mma16(acc[0][2 * nfp + 1], a[0], bk[2], bk[3]);
                mma16(acc[1][2 * nfp + 1], a[1], bk[2], bk[3]);
            }
        }
    }

    if (mode == 0) {
#pragma unroll
        for (int mf = 0; mf < 2; mf++) {
            int row = blockIdx.y * 128 + wm * 32 + mf * 16 + g;
#pragma unroll
            for (int nf = 0; nf < 8; nf++) {
                int col = blockIdx.x * 128 + wn * 64 + nf * 8 + 2 * t;
                float b0 = bias[col], b1 = bias[col + 1];
                *(float2*)(Cf + (size_t)row * N + col) =
                    make_float2(acc[mf][nf][0] + b0, acc[mf][nf][1] + b1);
                *(float2*)(Cf + (size_t)(row + 8) * N + col) =
                    make_float2(acc[mf][nf][2] + b0, acc[mf][nf][3] + b1);
            }
        }
    } else {
        // fused QKV epilogue: bias + split + rope -> [b,h,l,d] fp16
#pragma unroll
        for (int nf = 0; nf < 8; nf++) {
            const int cg = blockIdx.x * 128 + wn * 64 + nf * 8 + 2 * t;
            const int sec = cg >> 10;          // 0=q, 1=k, 2=v
            const int d10 = cg & 1023;
            const int h = d10 >> 6, d = d10 & 63;
            const float b0 = bias[cg], b1 = bias[cg + 1];
            float inv = 0.f;
            if (sec < 2)
                inv = powf(10000.0f, -(float)d / (float)DH);  // d even = 2*i
#pragma unroll
            for (int mf = 0; mf < 2; mf++) {
#pragma unroll
                for (int rr = 0; rr < 2; rr++) {
                    int row = blockIdx.y * 128 + wm * 32 + mf * 16 + g + rr * 8;
                    int b = row >> 11, l = row & (NL - 1);
                    float v0 = acc[mf][nf][2 * rr] + b0;
                    float v1 = acc[mf][nf][2 * rr + 1] + b1;
                    size_t o = ((size_t)(b * NH + h) * NL + l) * DH + d;
                    if (sec == 2) {
                        *(unsigned*)(vh + o) = pack2(v0, v1);
                    } else {
                        float sn, cs;
                        sincosf((float)l * inv, &sn, &cs);
                        unsigned w = pack2(v0 * cs - v1 * sn,
                                           v0 * sn + v1 * cs);
                        *(unsigned*)((sec == 0 ? qh : kh) + o) = w;
                    }
                }
            }
        }
    }
}

// ---------------------------------------------------------------------------
// FP16 flash attention, fixed-max softmax. q-tile 256 (8 warps x 32 rows),
// key-tile 64, cp.async double-buffered K/V, Q fragments hoisted to registers,
// K via ldmatrix, V via ldmatrix.trans, P fed to PV directly from S fragments.
// ---------------------------------------------------------------------------
#define QT 256
#define KT 64
#define STR 72   /* halfs per row */
#define SCL 0.1803368801111244f   /* 0.125 * log2(e) */

__global__ __launch_bounds__(256, 1) void attn_h(
    const __half* __restrict__ Qg, const __half* __restrict__ Kg,
    const __half* __restrict__ Vg, const int* __restrict__ amask,
    __half* __restrict__ outh)
{
    extern __shared__ __half sa[];
    const unsigned qs0 = (unsigned)__cvta_generic_to_shared(sa);
    const unsigned ks0 = qs0 + QT * STR * 2;
    const unsigned vs0 = ks0 + 2 * KT * STR * 2;
    float* msk = (float*)(sa + QT * STR + 4 * KT * STR);

    const int tid = threadIdx.x;
    const int lane = tid & 31, wid = tid >> 5;
    const int g = lane >> 2, t = lane & 3;
    const int qt = (gridDim.x - 1) - blockIdx.x;   // heavy tiles first
    const int bh = blockIdx.y;
    const int b = bh >> 4, h = bh & 15;
    const int q0 = qt * QT;
    const int ktmax = 4 * qt + 3;

    const __half* Qp = Qg + ((size_t)bh * NL + q0) * DH;
    const __half* Kp = Kg + (size_t)bh * NL * DH;
    const __half* Vp = Vg + (size_t)bh * NL * DH;

    auto copy_kv = [&](int kt_, int bf) {
        unsigned kd = ks0 + bf * (KT * STR * 2);
        unsigned vd = vs0 + bf * (KT * STR * 2);
        const __half* Ksrc = Kp + (size_t)kt_ * KT * DH;
        const __half* Vsrc = Vp + (size_t)kt_ * KT * DH;
#pragma unroll
        for (int i = 0; i < 2; i++) {
            int c = tid + i * 256;
            int r = c >> 3, o8 = (c & 7) * 8;
            cpa16(kd + (r * STR + o8) * 2, Ksrc + r * DH + o8);
            cpa16(vd + (r * STR + o8) * 2, Vsrc + r * DH + o8);
        }
        if (tid < KT)
            msk[bf * KT + tid] =
                amask[b * NL + kt_ * KT + tid] ? 0.f : -1e30f;
    };

    // prologue: Q + tile 0
#pragma unroll
    for (int i = 0; i < 8; i++) {
        int c = tid + i * 256;
        int r = c >> 3, o8 = (c & 7) * 8;
        cpa16(qs0 + (r * STR + o8) * 2, Qp + (size_t)r * DH + o8);
    }
    copy_kv(0, 0);
    CP_COMMIT();

    const int arow_l = ((lane >> 3) & 1) * 8 + (lane & 7);
    const int akoff_l = (lane >> 4) * 8;
    const int krow_l = ((lane >> 4) & 1) * 8 + (lane & 7);
    const int kkoff_l = ((lane >> 3) & 1) * 8;
    const int vkey_l = ((lane >> 4) & 1) * 8 + (lane & 7);
    const int vdoff_l = ((lane >> 3) & 1) * 8;

    unsigned qb[2];
#pragma unroll
    for (int mf = 0; mf < 2; mf++)
        qb[mf] = qs0 + ((wid * 32 + mf * 16 + arow_l) * STR + akoff_l) * 2;
    unsigned kbb[4], vbb[4];
#pragma unroll
    for (int j = 0; j < 4; j++) {
        kbb[j] = ks0 + ((j * 16 + krow_l) * STR + kkoff_l) * 2;
        vbb[j] = vs0 + (vkey_l * STR + j * 16 + vdoff_l) * 2;
    }
    const unsigned bufB = KT * STR * 2;

    float o[2][8][4];
#pragma unroll
    for (int mf = 0; mf < 2; mf++)
#pragma unroll
        for (int nf = 0; nf < 8; nf++)
#pragma unroll
            for (int i = 0; i < 4; i++) o[mf][nf][i] = 0.f;
    float l_acc[2][2] = {{0.f, 0.f}, {0.f, 0.f}};

    unsigned qreg[4][2][4];   // [kc][mf][frag] — hoisted Q
    int buf = 0;
    for (int kt = 0; kt <= ktmax; kt++) {
        if (kt < ktmax) {
            copy_kv(kt + 1, buf ^ 1);
            CP_COMMIT();
            CP_WAIT1();
        } else {
            CP_WAIT0();
        }
        __syncthreads();

        if (kt == 0) {
#pragma unroll
            for (int kc = 0; kc < 4; kc++) {
                ldsm4(qreg[kc][0], qb[0] + kc * 32);
                ldsm4(qreg[kc][1], qb[1] + kc * 32);
            }
        }

        const unsigned kofs = buf * bufB;
        const float* mb = msk + buf * KT;

        // ---- S = Q K^T ----
        float s[2][8][4];
#pragma unroll
        for (int mf = 0; mf < 2; mf++)
#pragma unroll
            for (int nf = 0; nf < 8; nf++)
#pragma unroll
                for (int i = 0; i < 4; i++) s[mf][nf][i] = 0.f;

#pragma unroll
        for (int kc = 0; kc < 4; kc++) {
            unsigned bk[4];
#pragma unroll
            for (int nfp = 0; nfp < 4; nfp++) {
                ldsm4(bk, kbb[nfp] + kofs + kc * 32);
                mma16(s[0][2 * nfp],     qreg[kc][0], bk[0], bk[1]);
                mma16(s[1][2 * nfp],     qreg[kc][1], bk[0], bk[1]);
                mma16(s[0][2 * nfp + 1], qreg[kc][0], bk[2], bk[3]);
                mma16(s[1][2 * nfp + 1], qreg[kc][1], bk[2], bk[3]);
            }
        }

        const bool diag = (kt * KT + KT - 1 > q0);

        // ---- fixed-max softmax: exp2(s*SCL + mask) ----
#pragma unroll
        for (int mf = 0; mf < 2; mf++) {
            const int rlo = q0 + wid * 32 + mf * 16 + g;
            const int rhi = rlo + 8;
            float sum0 = 0.f, sum1 = 0.f;
#pragma unroll
            for (int nf = 0; nf < 8; nf++) {
                int c = kt * KT + nf * 8 + 2 * t;
                float mk0 = mb[nf * 8 + 2 * t];
                float mk1 = mb[nf * 8 + 2 * t + 1];
                float* sv = s[mf][nf];
                sv[0] = sv[0] * SCL + mk0;
                sv[1] = sv[1] * SCL + mk1;
                sv[2] = sv[2] * SCL + mk0;
                sv[3] = sv[3] * SCL + mk1;
                if (diag) {
                    if (c     > rlo) sv[0] = -1e30f;
                    if (c + 1 > rlo) sv[1] = -1e30f;
                    if (c     > rhi) sv[2] = -1e30f;
                    if (c + 1 > rhi) sv[3] = -1e30f;
                }
                sv[0] = ex2(sv[0]); sum0 += sv[0];
                sv[1] = ex2(sv[1]); sum0 += sv[1];
                sv[2] = ex2(sv[2]); sum1 += sv[2];
                sv[3] = ex2(sv[3]); sum1 += sv[3];
            }
            l_acc[mf][0] += sum0;
            l_acc[mf][1] += sum1;
        }

        // ---- O += P V ----
#pragma unroll
        for (int kc = 0; kc < 4; kc++) {
            unsigned pa[2][4];
#pragma unroll
            for (int mf = 0; mf < 2; mf++) {
                pa[mf][0] = pack2(s[mf][2 * kc][0],     s[mf][2 * kc][1]);
                pa[mf][1] = pack2(s[mf][2 * kc][2],     s[mf][2 * kc][3]);
                pa[mf][2] = pack2(s[mf][2 * kc + 1][0], s[mf][2 * kc + 1][1]);
                pa[mf][3] = pack2(s[mf][2 * kc + 1][2], s[mf][2 * kc + 1][3]);
            }
#pragma unroll
            for (int db = 0; db < 4; db++) {
                unsigned bv[4];
                ldsm4t(bv, vbb[db] + kofs + kc * (16 * STR * 2));
                mma16(o[0][2 * db],     pa[0], bv[0], bv[2]);
                mma16(o[1][2 * db],     pa[1], bv[0], bv[2]);
                mma16(o[0][2 * db + 1], pa[0], bv[1], bv[3]);
                mma16(o[1][2 * db + 1], pa[1], bv[1], bv[3]);
            }
        }
        __syncthreads();
        buf ^= 1;
    }

    // ---- finalize ----
#pragma unroll
    for (int mf = 0; mf < 2; mf++) {
        float s0 = l_acc[mf][0], s1 = l_acc[mf][1];
        s0 += __shfl_xor_sync(0xffffffffu, s0, 1);
        s0 += __shfl_xor_sync(0xffffffffu, s0, 2);
        s1 += __shfl_xor_sync(0xffffffffu, s1, 1);
        s1 += __shfl_xor_sync(0xffffffffu, s1, 2);
        float inv0 = 1.f / s0, inv1 = 1.f / s1;
        int rlo = q0 + wid * 32 + mf * 16 + g;
        __half* op = outh + ((size_t)b * NL + rlo) * ND + h * DH;
#pragma unroll
        for (int nf = 0; nf < 8; nf++) {
            int col = nf * 8 + 2 * t;
            *(unsigned*)(op + col) =
                pack2(o[mf][nf][0] * inv0, o[mf][nf][1] * inv0);
            *(unsigned*)(op + (size_t)8 * ND + col) =
                pack2(o[mf][nf][2] * inv1, o[mf][nf][3] * inv1);
        }
    }
}

// ---------------------------------------------------------------------------
extern "C" void kernel_launch(void* const* d_in, const int* in_sizes, int n_in,
                              void* d_out, int out_size)
{
    const float* x     = (const float*)d_in[0];
    const float* Wqkv  = (const float*)d_in[1];
    const float* bqkv  = (const float*)d_in[2];
    const float* Wproj = (const float*)d_in[3];
    const float* bproj = (const float*)d_in[4];
    const int*   amask = (const int*)d_in[5];
    float* out = (float*)d_out;

    __half *xh, *wqkvh, *wprojh, *qh, *kh, *vh, *attnh;
    cudaGetSymbolAddress((void**)&xh,     g_xh);
    cudaGetSymbolAddress((void**)&wqkvh,  g_wqkvh);
    cudaGetSymbolAddress((void**)&wprojh, g_wprojh);
    cudaGetSymbolAddress((void**)&qh,     g_qh);
    cudaGetSymbolAddress((void**)&kh,     g_kh);
    cudaGetSymbolAddress((void**)&vh,     g_vh);
    cudaGetSymbolAddress((void**)&attnh,  g_attnh);

    const int attn_smem = (QT * STR + 4 * KT * STR) * 2 + 2 * KT * 4;
    cudaFuncSetAttribute(attn_h,
                         cudaFuncAttributeMaxDynamicSharedMemorySize,
                         attn_smem);

    // Prep: convert x, transpose+convert weights
    int n8 = (NB * NL * ND) / 8;
    conv_h<<<(n8 + 255) / 256, 256>>>(x, xh, n8);
    wtrans_h<<<dim3(ND3 / 32, ND / 32), 256>>>(Wqkv, wqkvh, ND, ND3);
    wtrans_h<<<dim3(ND / 32, ND / 32), 256>>>(Wproj, wprojh, ND, ND);

    // 1) QKV projection with fused bias+split+RoPE -> qh/kh/vh [b,h,l,d]
    gemm_h<<<dim3(ND3 / 128, (NB * NL) / 128), 256>>>(
        xh, wqkvh, bqkv, nullptr, qh, kh, vh, NB * NL, ND3, ND, 1);

    // 2) Attention -> fp16 [b,l,nd]
    attn_h<<<dim3(NL / QT, NB * NH), 256, attn_smem>>>(
        qh, kh, vh, amask, attnh);

    // 3) Output projection -> fp32
    gemm_h<<<dim3(ND / 128, (NB * NL) / 128), 256>>>(
        attnh, wprojh, bproj, out, nullptr, nullptr, nullptr,
        NB * NL, ND, ND, 0);
}